// round 1
// baseline (speedup 1.0000x reference)
#include <cuda_runtime.h>
#include <math.h>

// Problem constants
#define N_Uc   7
#define N_Ec   14
#define N_DETc 16
#define N_FBc  3
#define N_SVc  256
#define N_PVc  32
#define NPAIR  196     // N_E * N_E
#define N_ORB  112     // 7 * 16

// Shared memory layout (static, 45,984 B < 48 KB)
struct __align__(16) SmemLayout {
    float sv[N_Ec][N_SVc];     // 14*256 electron stream
    float pv[NPAIR * N_PVc];   // 196*32 pair stream; orbital phase reuses first 14*112 as orbm
    float scr[896];            // fb: pu[0..447]=14x32, pd[448..895]
                               // layer0: pin[0..783]=196x4, pu0[784..839]=14x4, pd0[840..895]
    float mu[N_SVc];
    float md[N_SVc];
    float sin8[N_Ec][8];       // one-electron input features
    float env[N_Ec];           // sum_a exp(-|r_e - a|)
    float rl[N_Ec][3];
    float ldet[32];
    float sgn[32];
};

__global__ void __launch_bounds__(256, 3)
ansatz_kernel(const float* __restrict__ r,
              const float* __restrict__ s_w0, const float* __restrict__ s_b0,
              const float* __restrict__ s_w,  const float* __restrict__ s_b,
              const float* __restrict__ p_w0, const float* __restrict__ p_b0,
              const float* __restrict__ p_w,  const float* __restrict__ p_b,
              const float* __restrict__ va_w, const float* __restrict__ va_b,
              const float* __restrict__ wu_w, const float* __restrict__ wu_b,
              const float* __restrict__ wd_w, const float* __restrict__ wd_b,
              const float* __restrict__ wf_w,
              float* __restrict__ out, int nb)
{
    __shared__ SmemLayout s;
    const int t = threadIdx.x;
    const int b = blockIdx.x;
    if (b >= nb) return;
    const float inv7 = 1.0f / 7.0f;

    // ---------------- Phase 0: geometry features ----------------
    for (int q = t; q < N_Ec * 3; q += 256)
        ((float*)s.rl)[q] = r[b * (N_Ec * 3) + q];
    __syncthreads();

    if (t < N_Ec) {
        float x = s.rl[t][0], y = s.rl[t][1], z = s.rl[t][2];
        float ev = 0.f;
        #pragma unroll
        for (int a = 0; a < 2; ++a) {
            float dz = z - (a ? 1.4f : 0.0f);
            float len = sqrtf(x * x + y * y + dz * dz);
            s.sin8[t][a * 4 + 0] = x;
            s.sin8[t][a * 4 + 1] = y;
            s.sin8[t][a * 4 + 2] = dz;
            s.sin8[t][a * 4 + 3] = len;
            ev += expf(-len);
        }
        s.env[t] = ev;
    }
    if (t < NPAIR) {
        int i = t / 14, j = t - i * 14;
        float dx = s.rl[j][0] - s.rl[i][0];
        float dy = s.rl[j][1] - s.rl[i][1];
        float dz = s.rl[j][2] - s.rl[i][2];
        float ax = dx, ay = dy, az = dz;
        if (i == j) { ax += 1.f; ay += 1.f; az += 1.f; }  // rr + eye (only in the norm)
        float len = sqrtf(ax * ax + ay * ay + az * az);
        float* pin = s.scr;
        pin[t * 4 + 0] = dx; pin[t * 4 + 1] = dy;
        pin[t * 4 + 2] = dz; pin[t * 4 + 3] = len;
    }
    __syncthreads();

    // layer-0 means: mu0/md0 (8 dims), pu0/pd0 (14 x 4)
    if (t < 16) {
        int k = t & 7;
        int e0 = (t < 8) ? 0 : 7;
        float su = 0.f;
        #pragma unroll
        for (int e = 0; e < 7; ++e) su += s.sin8[e0 + e][k];
        ((t < 8) ? s.mu : s.md)[k] = su * inv7;
    }
    if (t >= 64 && t < 176) {
        int q = t - 64;
        int dn = (q >= 56) ? 1 : 0;
        int qq = q - dn * 56;
        int e = qq >> 2, k = qq & 3;
        int i0 = dn ? 7 : 0;
        const float* pin = s.scr;
        float su = 0.f;
        #pragma unroll
        for (int ii = 0; ii < 7; ++ii) su += pin[((i0 + ii) * 14 + e) * 4 + k];
        s.scr[784 + dn * 56 + e * 4 + k] = su * inv7;
    }
    __syncthreads();

    // ---------------- Layer 0 ----------------
    {
        // pair stream: thread t owns pair row t
        float pnew[32];
        const bool prow = (t < NPAIR);
        if (prow) {
            const float* pin = s.scr + t * 4;
            float r0 = pin[0], r1 = pin[1], r2 = pin[2], r3 = pin[3];
            #pragma unroll
            for (int c2 = 0; c2 < 32; ++c2) {
                float v = p_b0[c2]
                        + r0 * p_w0[0 * 32 + c2] + r1 * p_w0[1 * 32 + c2]
                        + r2 * p_w0[2 * 32 + c2] + r3 * p_w0[3 * 32 + c2];
                pnew[c2] = tanhf(v);
            }
        }
        // electron stream: column c = t
        const int c = t;
        float cm = s_b0[c];
        #pragma unroll
        for (int k = 0; k < 8; ++k)
            cm += s.mu[k] * s_w0[(8 + k) * 256 + c] + s.md[k] * s_w0[(16 + k) * 256 + c];
        float acc[N_Ec];
        #pragma unroll
        for (int e = 0; e < N_Ec; ++e) acc[e] = cm;
        #pragma unroll
        for (int k = 0; k < 8; ++k) {
            float w = s_w0[k * 256 + c];
            #pragma unroll
            for (int e = 0; e < N_Ec; ++e) acc[e] += s.sin8[e][k] * w;
        }
        const float* pu0 = s.scr + 784;
        const float* pd0 = s.scr + 840;
        #pragma unroll
        for (int k = 0; k < 4; ++k) {
            float wu = s_w0[(24 + k) * 256 + c];
            float wd2 = s_w0[(28 + k) * 256 + c];
            #pragma unroll
            for (int e = 0; e < N_Ec; ++e)
                acc[e] += pu0[e * 4 + k] * wu + pd0[e * 4 + k] * wd2;
        }
        if (prow) {
            #pragma unroll
            for (int c2 = 0; c2 < 32; ++c2) s.pv[t * 32 + c2] = pnew[c2];
        }
        #pragma unroll
        for (int e = 0; e < N_Ec; ++e) s.sv[e][c] = tanhf(acc[e]);
    }
    __syncthreads();

    // ---------------- FB layers (il<3) + final va projection (il==3) ----------------
    for (int il = 0; il <= N_FBc; ++il) {
        const bool last = (il == N_FBc);
        const float* WL = last ? va_w : (s_w + il * (832 * 256));
        const float* bL = last ? va_b : (s_b + il * 256);
        const float* PW = p_w + il * (32 * 32);
        const float* Pb = p_b + il * 32;

        // (a) means over electrons: mu/md (256), pu/pd (14x32)
        {
            const int c = t;
            float su = 0.f, sd = 0.f;
            #pragma unroll
            for (int e = 0; e < 7; ++e) { su += s.sv[e][c]; sd += s.sv[7 + e][c]; }
            s.mu[c] = su * inv7;
            s.md[c] = sd * inv7;
        }
        for (int idx = t; idx < 896; idx += 256) {
            int dn = (idx >= 448) ? 1 : 0;
            int q = idx - dn * 448;
            int e = q >> 5, k = q & 31;
            int i0 = dn ? 7 : 0;
            float su = 0.f;
            #pragma unroll
            for (int ii = 0; ii < 7; ++ii) su += s.pv[((i0 + ii) * 14 + e) * 32 + k];
            s.scr[idx] = su * inv7;
        }
        __syncthreads();

        // (b) pair GEMM (not after the last fb layer); row-owner threads, no staging needed
        if (!last && t < NPAIR) {
            float row[32];
            #pragma unroll
            for (int k = 0; k < 32; ++k) row[k] = s.pv[t * 32 + k];
            float o[32];
            #pragma unroll
            for (int c2 = 0; c2 < 32; ++c2) o[c2] = Pb[c2];
            #pragma unroll
            for (int k = 0; k < 32; ++k) {
                float rk = row[k];
                #pragma unroll
                for (int c2 = 0; c2 < 32; c2 += 4) {
                    float4 w4 = *reinterpret_cast<const float4*>(&PW[k * 32 + c2]);
                    o[c2 + 0] += rk * w4.x; o[c2 + 1] += rk * w4.y;
                    o[c2 + 2] += rk * w4.z; o[c2 + 3] += rk * w4.w;
                }
            }
            #pragma unroll
            for (int c2 = 0; c2 < 32; ++c2)
                s.pv[t * 32 + c2] = tanhf(o[c2]) + row[c2];
        }

        // (c) electron GEMM, column-stationary (c = t)
        const int c = t;
        float cma = bL[c], cmb = 0.f;
        const float* Wmu = WL + 256 * 256 + c;
        const float* Wmd = WL + 512 * 256 + c;
        #pragma unroll 2
        for (int k = 0; k < 256; k += 4) {
            float4 m4 = *reinterpret_cast<const float4*>(&s.mu[k]);
            float4 n4 = *reinterpret_cast<const float4*>(&s.md[k]);
            cma = fmaf(m4.x, Wmu[(k + 0) * 256], cma);
            cmb = fmaf(m4.y, Wmu[(k + 1) * 256], cmb);
            cma = fmaf(m4.z, Wmu[(k + 2) * 256], cma);
            cmb = fmaf(m4.w, Wmu[(k + 3) * 256], cmb);
            cma = fmaf(n4.x, Wmd[(k + 0) * 256], cma);
            cmb = fmaf(n4.y, Wmd[(k + 1) * 256], cmb);
            cma = fmaf(n4.z, Wmd[(k + 2) * 256], cma);
            cmb = fmaf(n4.w, Wmd[(k + 3) * 256], cmb);
        }
        float acc[N_Ec];
        const float cm = cma + cmb;
        #pragma unroll
        for (int e = 0; e < N_Ec; ++e) acc[e] = cm;

        const float* Ws = WL + c;
        #pragma unroll 2
        for (int k = 0; k < 256; k += 4) {
            float w0 = Ws[(k + 0) * 256], w1 = Ws[(k + 1) * 256];
            float w2 = Ws[(k + 2) * 256], w3 = Ws[(k + 3) * 256];
            #pragma unroll
            for (int e = 0; e < N_Ec; ++e) {
                float4 s4 = *reinterpret_cast<const float4*>(&s.sv[e][k]);
                acc[e] = fmaf(s4.w, w3, fmaf(s4.z, w2, fmaf(s4.y, w1, fmaf(s4.x, w0, acc[e]))));
            }
        }
        const float* Wpu = WL + 768 * 256 + c;
        const float* Wpd = WL + 800 * 256 + c;
        #pragma unroll
        for (int k = 0; k < 32; k += 4) {
            float u0 = Wpu[(k + 0) * 256], u1 = Wpu[(k + 1) * 256];
            float u2 = Wpu[(k + 2) * 256], u3 = Wpu[(k + 3) * 256];
            float v0 = Wpd[(k + 0) * 256], v1 = Wpd[(k + 1) * 256];
            float v2 = Wpd[(k + 2) * 256], v3 = Wpd[(k + 3) * 256];
            #pragma unroll
            for (int e = 0; e < N_Ec; ++e) {
                float4 a4 = *reinterpret_cast<const float4*>(&s.scr[e * 32 + k]);
                float4 b4 = *reinterpret_cast<const float4*>(&s.scr[448 + e * 32 + k]);
                acc[e] += a4.x * u0 + a4.y * u1 + a4.z * u2 + a4.w * u3
                        + b4.x * v0 + b4.y * v1 + b4.z * v2 + b4.w * v3;
            }
        }
        float nv[N_Ec];
        #pragma unroll
        for (int e = 0; e < N_Ec; ++e)
            nv[e] = tanhf(acc[e]) + (last ? 0.f : s.sv[e][c]);
        __syncthreads();
        #pragma unroll
        for (int e = 0; e < N_Ec; ++e) s.sv[e][c] = nv[e];
        __syncthreads();
    }

    // ---------------- Orbitals: sv @ {wu,wd} * env  (into s.pv as orbm[14][112]) ----------------
    for (int idx = t; idx < N_Ec * N_ORB; idx += 256) {
        int e = idx / N_ORB, o = idx - e * N_ORB;
        const float* W = (e < 7) ? wu_w : wd_w;
        float v = (e < 7) ? wu_b[o] : wd_b[o];
        #pragma unroll 2
        for (int k = 0; k < 256; k += 4) {
            float4 s4 = *reinterpret_cast<const float4*>(&s.sv[e][k]);
            v = fmaf(s4.x, W[(k + 0) * N_ORB + o],
                fmaf(s4.y, W[(k + 1) * N_ORB + o],
                fmaf(s4.z, W[(k + 2) * N_ORB + o],
                fmaf(s4.w, W[(k + 3) * N_ORB + o], v))));
        }
        s.pv[idx] = v * s.env[e];
    }
    __syncthreads();

    // ---------------- 32 slogdets of 7x7 (register LU, compile-time pivot indices) ----------------
    if (t < 32) {
        const int sp = t >> 4, d = t & 15;
        float m[7][7];
        #pragma unroll
        for (int j = 0; j < 7; ++j)
            #pragma unroll
            for (int i = 0; i < 7; ++i)
                m[j][i] = s.pv[(sp * 7 + i) * N_ORB + j * 16 + d];

        float ld = 0.f, sg = 1.f;
        #pragma unroll
        for (int col = 0; col < 7; ++col) {
            // bubble-style partial pivoting with compile-time indices
            #pragma unroll
            for (int rr = col + 1; rr < 7; ++rr) {
                if (fabsf(m[rr][col]) > fabsf(m[col][col])) {
                    sg = -sg;
                    #pragma unroll
                    for (int cc = 0; cc < 7; ++cc) {
                        float tmp = m[col][cc]; m[col][cc] = m[rr][cc]; m[rr][cc] = tmp;
                    }
                }
            }
            float piv = m[col][col];
            sg = (piv < 0.f) ? -sg : sg;
            ld += logf(fabsf(piv));
            float inv = 1.f / piv;
            #pragma unroll
            for (int rr = col + 1; rr < 7; ++rr) {
                float f = m[rr][col] * inv;
                #pragma unroll
                for (int cc = col + 1; cc < 7; ++cc)
                    m[rr][cc] -= f * m[col][cc];
            }
        }
        s.ldet[t] = ld;
        s.sgn[t] = sg;
    }
    __syncthreads();

    // ---------------- combine: logsumexp over dets ----------------
    if (t == 0) {
        float l[16], mx = -3.4e38f;
        #pragma unroll
        for (int d = 0; d < 16; ++d) {
            l[d] = s.ldet[d] + s.ldet[16 + d];
            mx = fmaxf(mx, l[d]);
        }
        float psi = 0.f;
        #pragma unroll
        for (int d = 0; d < 16; ++d)
            psi += s.sgn[d] * s.sgn[16 + d] * expf(l[d] - mx) * wf_w[d];
        out[b] = logf(fabsf(psi)) + mx;
    }
}

extern "C" void kernel_launch(void* const* d_in, const int* in_sizes, int n_in,
                              void* d_out, int out_size)
{
    const float* r    = (const float*)d_in[0];
    const float* s_w0 = (const float*)d_in[1];
    const float* s_b0 = (const float*)d_in[2];
    const float* s_w  = (const float*)d_in[3];
    const float* s_b  = (const float*)d_in[4];
    const float* p_w0 = (const float*)d_in[5];
    const float* p_b0 = (const float*)d_in[6];
    const float* p_w  = (const float*)d_in[7];
    const float* p_b  = (const float*)d_in[8];
    const float* va_w = (const float*)d_in[9];
    const float* va_b = (const float*)d_in[10];
    const float* wu_w = (const float*)d_in[11];
    const float* wu_b = (const float*)d_in[12];
    const float* wd_w = (const float*)d_in[13];
    const float* wd_b = (const float*)d_in[14];
    const float* wf_w = (const float*)d_in[15];

    const int nb = in_sizes[0] / (14 * 3);
    ansatz_kernel<<<nb, 256>>>(r, s_w0, s_b0, s_w, s_b, p_w0, p_b0, p_w, p_b,
                               va_w, va_b, wu_w, wu_b, wd_w, wd_b, wf_w,
                               (float*)d_out, nb);
}

// round 2
// speedup vs baseline: 1.2657x; 1.2657x over previous
#include <cuda_runtime.h>
#include <math.h>

#define NE    14
#define NSV   256
#define NPVs  33      // padded pair-row stride (bank-conflict-free)
#define NPAIR 196
#define NORB  112
#define NFB   3

struct __align__(16) Smem {
    float sv[NE][NSV];          // 14336 B electron stream
    float pv[NPAIR * NPVs];     // 25872 B pair stream; reused as orbm[14][112] (swizzled)
    float scr[896];             // pu/pd means; layer0: pin + pu0/pd0
    float mumd[512];            // mu | md
    float cm[256];              // swizzled rank-1 contribution (incl bias)
    float red[NE * NSV];        // swizzled k-split reduction buffer
    float sin8[NE][8];
    float env[NE];
    float rl[NE][3];
    float ldet[32];
    float sgn[32];
};

union U64 { unsigned long long u; float2 f; };

__device__ __forceinline__ void ffma2(unsigned long long &d, unsigned long long a, unsigned long long b) {
    asm("fma.rn.f32x2 %0, %1, %2, %0;" : "+l"(d) : "l"(a), "l"(b));
}
__device__ __forceinline__ unsigned long long dup2(float x) {
    unsigned long long r;
    asm("mov.b64 %0, {%1, %1};" : "=l"(r) : "f"(x));
    return r;
}
__device__ __forceinline__ int swz(int c) { return c ^ (c >> 5); }   // bijective on [0,256), CF both ways

__global__ void __launch_bounds__(256, 2)
ansatz_kernel(const float* __restrict__ r,
              const float* __restrict__ s_w0, const float* __restrict__ s_b0,
              const float* __restrict__ s_w,  const float* __restrict__ s_b,
              const float* __restrict__ p_w0, const float* __restrict__ p_b0,
              const float* __restrict__ p_w,  const float* __restrict__ p_b,
              const float* __restrict__ va_w, const float* __restrict__ va_b,
              const float* __restrict__ wu_w, const float* __restrict__ wu_b,
              const float* __restrict__ wd_w, const float* __restrict__ wd_b,
              const float* __restrict__ wf_w,
              float* __restrict__ out, int nb)
{
    extern __shared__ char smem_raw[];
    Smem& s = *reinterpret_cast<Smem*>(smem_raw);

    const int t    = threadIdx.x;
    const int b    = blockIdx.x;
    const int lane = t & 31;
    const int wid  = t >> 5;
    const int eh   = wid >> 2;      // electron half: 0 -> e 0..6, 1 -> e 7..13
    const int kh   = wid & 3;       // k quarter
    const int e0   = eh * 7;
    const int c0   = lane * 8;      // 8 output columns per lane
    if (b >= nb) return;
    const float inv7 = 1.0f / 7.0f;

    // ---------------- Phase 0: geometry features ----------------
    for (int q = t; q < NE * 3; q += 256)
        ((float*)s.rl)[q] = r[b * (NE * 3) + q];
    __syncthreads();

    if (t < NE) {
        float x = s.rl[t][0], y = s.rl[t][1], z = s.rl[t][2];
        float ev = 0.f;
        #pragma unroll
        for (int a = 0; a < 2; ++a) {
            float dz = z - (a ? 1.4f : 0.0f);
            float len = sqrtf(x * x + y * y + dz * dz);
            s.sin8[t][a * 4 + 0] = x;
            s.sin8[t][a * 4 + 1] = y;
            s.sin8[t][a * 4 + 2] = dz;
            s.sin8[t][a * 4 + 3] = len;
            ev += expf(-len);
        }
        s.env[t] = ev;
    }
    if (t < NPAIR) {
        int i = t / 14, j = t - i * 14;
        float dx = s.rl[j][0] - s.rl[i][0];
        float dy = s.rl[j][1] - s.rl[i][1];
        float dz = s.rl[j][2] - s.rl[i][2];
        float ax = dx, ay = dy, az = dz;
        if (i == j) { ax += 1.f; ay += 1.f; az += 1.f; }
        float len = sqrtf(ax * ax + ay * ay + az * az);
        s.scr[t * 4 + 0] = dx; s.scr[t * 4 + 1] = dy;
        s.scr[t * 4 + 2] = dz; s.scr[t * 4 + 3] = len;
    }
    __syncthreads();

    // layer-0 means
    if (t < 16) {
        int k = t & 7;
        int ee0 = (t < 8) ? 0 : 7;
        float su = 0.f;
        #pragma unroll
        for (int e = 0; e < 7; ++e) su += s.sin8[ee0 + e][k];
        s.mumd[(t < 8 ? 0 : 8) + k] = su * inv7;   // mu0 at [0..7], md0 at [8..15]
    }
    if (t >= 64 && t < 176) {
        int q = t - 64;
        int dn = (q >= 56) ? 1 : 0;
        int qq = q - dn * 56;
        int e = qq >> 2, k = qq & 3;
        int i0 = dn ? 7 : 0;
        float su = 0.f;
        #pragma unroll
        for (int ii = 0; ii < 7; ++ii) su += s.scr[((i0 + ii) * 14 + e) * 4 + k];
        s.scr[784 + dn * 56 + e * 4 + k] = su * inv7;
    }
    __syncthreads();

    // ---------------- Layer 0 (small input layer, scalar path) ----------------
    {
        float pnew[32];
        const bool prow = (t < NPAIR);
        if (prow) {
            const float* pin = s.scr + t * 4;
            float r0 = pin[0], r1 = pin[1], r2 = pin[2], r3 = pin[3];
            #pragma unroll
            for (int c2 = 0; c2 < 32; ++c2) {
                float v = p_b0[c2]
                        + r0 * p_w0[0 * 32 + c2] + r1 * p_w0[1 * 32 + c2]
                        + r2 * p_w0[2 * 32 + c2] + r3 * p_w0[3 * 32 + c2];
                pnew[c2] = tanhf(v);
            }
        }
        const int c = t;
        float cm0 = s_b0[c];
        #pragma unroll
        for (int k = 0; k < 8; ++k)
            cm0 += s.mumd[k] * s_w0[(8 + k) * 256 + c] + s.mumd[8 + k] * s_w0[(16 + k) * 256 + c];
        float acc[NE];
        #pragma unroll
        for (int e = 0; e < NE; ++e) acc[e] = cm0;
        #pragma unroll
        for (int k = 0; k < 8; ++k) {
            float w = s_w0[k * 256 + c];
            #pragma unroll
            for (int e = 0; e < NE; ++e) acc[e] += s.sin8[e][k] * w;
        }
        const float* pu0 = s.scr + 784;
        const float* pd0 = s.scr + 840;
        #pragma unroll
        for (int k = 0; k < 4; ++k) {
            float wuv = s_w0[(24 + k) * 256 + c];
            float wdv = s_w0[(28 + k) * 256 + c];
            #pragma unroll
            for (int e = 0; e < NE; ++e)
                acc[e] += pu0[e * 4 + k] * wuv + pd0[e * 4 + k] * wdv;
        }
        if (prow) {
            #pragma unroll
            for (int c2 = 0; c2 < 32; ++c2) s.pv[t * NPVs + c2] = pnew[c2];
        }
        #pragma unroll
        for (int e = 0; e < NE; ++e) s.sv[e][c] = tanhf(acc[e]);
    }
    __syncthreads();

    // ---------------- FB layers (il<3) + final va projection (il==3) ----------------
    for (int il = 0; il <= NFB; ++il) {
        const bool last = (il == NFB);
        const float* WL = last ? va_w : (s_w + il * (832 * 256));
        const float* bL = last ? va_b : (s_b + il * 256);
        const float* PW = p_w + il * (32 * 32);
        const float* Pb = p_b + il * 32;

        // (a) means + init cm + zero red
        {
            const int c = t;
            float su = 0.f, sd = 0.f;
            #pragma unroll
            for (int e = 0; e < 7; ++e) { su += s.sv[e][c]; sd += s.sv[7 + e][c]; }
            s.mumd[c]       = su * inv7;
            s.mumd[256 + c] = sd * inv7;
            s.cm[swz(c)]    = bL[c];
        }
        for (int idx = t; idx < 896; idx += 256) {
            int dn = (idx >= 448) ? 1 : 0;
            int q = idx - dn * 448;
            int e = q >> 5, k = q & 31;
            int i0 = dn ? 7 : 0;
            float su = 0.f;
            #pragma unroll
            for (int ii = 0; ii < 7; ++ii) su += s.pv[((i0 + ii) * 14 + e) * NPVs + k];
            s.scr[idx] = su * inv7;
        }
        for (int q = t; q < NE * NSV; q += 256) s.red[q] = 0.f;
        __syncthreads();

        // (b) pair GEMM (packed f32x2), thread owns one pair row
        if (!last && t < NPAIR) {
            float row[32];
            #pragma unroll
            for (int k = 0; k < 32; ++k) row[k] = s.pv[t * NPVs + k];
            unsigned long long o[16];
            const ulonglong2* pb2 = (const ulonglong2*)Pb;
            #pragma unroll
            for (int q = 0; q < 8; ++q) {
                ulonglong2 bv = pb2[q];
                o[2 * q] = bv.x; o[2 * q + 1] = bv.y;
            }
            #pragma unroll
            for (int k = 0; k < 32; ++k) {
                unsigned long long rk = dup2(row[k]);
                const ulonglong2* w2 = (const ulonglong2*)(PW + k * 32);
                #pragma unroll
                for (int q = 0; q < 8; ++q) {
                    ulonglong2 wv = w2[q];
                    ffma2(o[2 * q], rk, wv.x);
                    ffma2(o[2 * q + 1], rk, wv.y);
                }
            }
            #pragma unroll
            for (int q = 0; q < 16; ++q) {
                U64 u; u.u = o[q];
                s.pv[t * NPVs + 2 * q]     = tanhf(u.f.x) + row[2 * q];
                s.pv[t * NPVs + 2 * q + 1] = tanhf(u.f.y) + row[2 * q + 1];
            }
        }

        // (c) rank-1 cm GEMM: warp wid handles rows [wid*64, wid*64+64) of 512
        {
            unsigned long long ca0 = 0, ca1 = 0, ca2 = 0, ca3 = 0;
            const int kbase = wid * 64;
            #pragma unroll 4
            for (int kk = 0; kk < 64; ++kk) {
                const int k = kbase + kk;
                const float* wp = WL + (256 + k) * 256 + c0;
                ulonglong2 w01 = *(const ulonglong2*)wp;
                ulonglong2 w23 = *(const ulonglong2*)(wp + 4);
                unsigned long long x2 = dup2(s.mumd[k]);
                ffma2(ca0, x2, w01.x); ffma2(ca1, x2, w01.y);
                ffma2(ca2, x2, w23.x); ffma2(ca3, x2, w23.y);
            }
            U64 u;
            u.u = ca0; atomicAdd(&s.cm[swz(c0 + 0)], u.f.x); atomicAdd(&s.cm[swz(c0 + 1)], u.f.y);
            u.u = ca1; atomicAdd(&s.cm[swz(c0 + 2)], u.f.x); atomicAdd(&s.cm[swz(c0 + 3)], u.f.y);
            u.u = ca2; atomicAdd(&s.cm[swz(c0 + 4)], u.f.x); atomicAdd(&s.cm[swz(c0 + 5)], u.f.y);
            u.u = ca3; atomicAdd(&s.cm[swz(c0 + 6)], u.f.x); atomicAdd(&s.cm[swz(c0 + 7)], u.f.y);
        }

        // (d) main electron GEMM: warp (eh, kh), Te=7, Tc=8, packed f32x2
        {
            unsigned long long acc[7][4];
            #pragma unroll
            for (int i = 0; i < 7; ++i)
                #pragma unroll
                for (int p = 0; p < 4; ++p) acc[i][p] = 0ull;

            const int kb = kh * 64;
            #pragma unroll 4
            for (int kk = 0; kk < 64; ++kk) {
                const int k = kb + kk;
                const float* wp = WL + k * 256 + c0;
                ulonglong2 w01 = *(const ulonglong2*)wp;
                ulonglong2 w23 = *(const ulonglong2*)(wp + 4);
                #pragma unroll
                for (int i = 0; i < 7; ++i) {
                    unsigned long long s2 = dup2(s.sv[e0 + i][k]);
                    ffma2(acc[i][0], s2, w01.x); ffma2(acc[i][1], s2, w01.y);
                    ffma2(acc[i][2], s2, w23.x); ffma2(acc[i][3], s2, w23.y);
                }
            }
            // pu/pd extension rows: kh handles k in [kh*8, kh*8+8)
            #pragma unroll
            for (int kk = 0; kk < 8; ++kk) {
                const int k = kh * 8 + kk;
                {
                    const float* wp = WL + (768 + k) * 256 + c0;
                    ulonglong2 w01 = *(const ulonglong2*)wp;
                    ulonglong2 w23 = *(const ulonglong2*)(wp + 4);
                    #pragma unroll
                    for (int i = 0; i < 7; ++i) {
                        unsigned long long s2 = dup2(s.scr[(e0 + i) * 32 + k]);
                        ffma2(acc[i][0], s2, w01.x); ffma2(acc[i][1], s2, w01.y);
                        ffma2(acc[i][2], s2, w23.x); ffma2(acc[i][3], s2, w23.y);
                    }
                }
                {
                    const float* wp = WL + (800 + k) * 256 + c0;
                    ulonglong2 w01 = *(const ulonglong2*)wp;
                    ulonglong2 w23 = *(const ulonglong2*)(wp + 4);
                    #pragma unroll
                    for (int i = 0; i < 7; ++i) {
                        unsigned long long s2 = dup2(s.scr[448 + (e0 + i) * 32 + k]);
                        ffma2(acc[i][0], s2, w01.x); ffma2(acc[i][1], s2, w01.y);
                        ffma2(acc[i][2], s2, w23.x); ffma2(acc[i][3], s2, w23.y);
                    }
                }
            }
            // k-split reduction via swizzled shared atomics (conflict-free banks)
            #pragma unroll
            for (int i = 0; i < 7; ++i) {
                #pragma unroll
                for (int p = 0; p < 4; ++p) {
                    U64 u; u.u = acc[i][p];
                    atomicAdd(&s.red[(e0 + i) * NSV + swz(c0 + 2 * p)],     u.f.x);
                    atomicAdd(&s.red[(e0 + i) * NSV + swz(c0 + 2 * p + 1)], u.f.y);
                }
            }
        }
        __syncthreads();

        // (e) epilogue: tanh + residual, one column per thread
        {
            const int c = t;
            const int cs = swz(c);
            const float cmv = s.cm[cs];
            #pragma unroll
            for (int e = 0; e < NE; ++e) {
                float v = tanhf(s.red[e * NSV + cs] + cmv);
                s.sv[e][c] = last ? v : (v + s.sv[e][c]);
            }
        }
        __syncthreads();
    }

    // ---------------- Orbitals: sv @ {wu,wd} * env into s.pv as orbm (swizzled) ----------------
    for (int idx = t; idx < NE * NORB; idx += 256) {
        int e = idx / NORB, o = idx - e * NORB;
        s.pv[e * NORB + (o ^ (o >> 5))] = (e < 7) ? wu_b[o] : wd_b[o];
    }
    __syncthreads();
    {
        const int oc0 = lane * 4;
        if (oc0 < NORB) {
            const float* W = eh ? wd_w : wu_w;
            unsigned long long oa[7][2];
            #pragma unroll
            for (int i = 0; i < 7; ++i) { oa[i][0] = 0ull; oa[i][1] = 0ull; }
            const int kb = kh * 64;
            #pragma unroll 4
            for (int kk = 0; kk < 64; ++kk) {
                const int k = kb + kk;
                ulonglong2 wv = *(const ulonglong2*)(W + k * NORB + oc0);
                #pragma unroll
                for (int i = 0; i < 7; ++i) {
                    unsigned long long s2 = dup2(s.sv[e0 + i][k]);
                    ffma2(oa[i][0], s2, wv.x);
                    ffma2(oa[i][1], s2, wv.y);
                }
            }
            #pragma unroll
            for (int i = 0; i < 7; ++i) {
                #pragma unroll
                for (int p = 0; p < 2; ++p) {
                    U64 u; u.u = oa[i][p];
                    int o0 = oc0 + 2 * p;
                    atomicAdd(&s.pv[(e0 + i) * NORB + (o0 ^ (o0 >> 5))], u.f.x);
                    atomicAdd(&s.pv[(e0 + i) * NORB + ((o0 + 1) ^ ((o0 + 1) >> 5))], u.f.y);
                }
            }
        }
    }
    __syncthreads();
    for (int idx = t; idx < NE * NORB; idx += 256) {
        int e = idx / NORB;
        s.pv[idx] *= s.env[e];
    }
    __syncthreads();

    // ---------------- 32 slogdets of 7x7 (register LU, compile-time pivots) ----------------
    if (t < 32) {
        const int sp = t >> 4, d = t & 15;
        float m[7][7];
        #pragma unroll
        for (int j = 0; j < 7; ++j) {
            int o = j * 16 + d;
            int og = o ^ (o >> 5);
            #pragma unroll
            for (int i = 0; i < 7; ++i)
                m[j][i] = s.pv[(sp * 7 + i) * NORB + og];
        }
        float ld = 0.f, sg = 1.f;
        #pragma unroll
        for (int col = 0; col < 7; ++col) {
            #pragma unroll
            for (int rr = col + 1; rr < 7; ++rr) {
                if (fabsf(m[rr][col]) > fabsf(m[col][col])) {
                    sg = -sg;
                    #pragma unroll
                    for (int cc = 0; cc < 7; ++cc) {
                        float tmp = m[col][cc]; m[col][cc] = m[rr][cc]; m[rr][cc] = tmp;
                    }
                }
            }
            float piv = m[col][col];
            sg = (piv < 0.f) ? -sg : sg;
            ld += logf(fabsf(piv));
            float inv = 1.f / piv;
            #pragma unroll
            for (int rr = col + 1; rr < 7; ++rr) {
                float f = m[rr][col] * inv;
                #pragma unroll
                for (int cc = col + 1; cc < 7; ++cc)
                    m[rr][cc] -= f * m[col][cc];
            }
        }
        s.ldet[t] = ld;
        s.sgn[t] = sg;
    }
    __syncthreads();

    if (t == 0) {
        float l[16], mx = -3.4e38f;
        #pragma unroll
        for (int d = 0; d < 16; ++d) {
            l[d] = s.ldet[d] + s.ldet[16 + d];
            mx = fmaxf(mx, l[d]);
        }
        float psi = 0.f;
        #pragma unroll
        for (int d = 0; d < 16; ++d)
            psi += s.sgn[d] * s.sgn[16 + d] * expf(l[d] - mx) * wf_w[d];
        out[b] = logf(fabsf(psi)) + mx;
    }
}

extern "C" void kernel_launch(void* const* d_in, const int* in_sizes, int n_in,
                              void* d_out, int out_size)
{
    const float* r    = (const float*)d_in[0];
    const float* s_w0 = (const float*)d_in[1];
    const float* s_b0 = (const float*)d_in[2];
    const float* s_w  = (const float*)d_in[3];
    const float* s_b  = (const float*)d_in[4];
    const float* p_w0 = (const float*)d_in[5];
    const float* p_b0 = (const float*)d_in[6];
    const float* p_w  = (const float*)d_in[7];
    const float* p_b  = (const float*)d_in[8];
    const float* va_w = (const float*)d_in[9];
    const float* va_b = (const float*)d_in[10];
    const float* wu_w = (const float*)d_in[11];
    const float* wu_b = (const float*)d_in[12];
    const float* wd_w = (const float*)d_in[13];
    const float* wd_b = (const float*)d_in[14];
    const float* wf_w = (const float*)d_in[15];

    const int nb = in_sizes[0] / (14 * 3);
    const int smem = (int)sizeof(Smem);
    cudaFuncSetAttribute(ansatz_kernel, cudaFuncAttributeMaxDynamicSharedMemorySize, smem);
    ansatz_kernel<<<nb, 256, smem>>>(r, s_w0, s_b0, s_w, s_b, p_w0, p_b0, p_w, p_b,
                                     va_w, va_b, wu_w, wu_b, wd_w, wd_b, wf_w,
                                     (float*)d_out, nb);
}

// round 4
// speedup vs baseline: 1.3759x; 1.0871x over previous
#include <cuda_runtime.h>
#include <math.h>

#define NE    14
#define NSV   256
#define NPVs  33
#define NPAIR 196
#define NORB  112
#define NFB   3

struct __align__(16) Smem {
    float sv[2][NE][NSV];        // 28672 B
    float pv[2][NPAIR * NPVs];   // 51744 B (reused as orbm[14][112] swizzled)
    float scr[2][896];           // pu/pd means; layer0: pin + pu0/pd0
    float mumd[2][512];          // mu | md
    float cm[2][NSV];            // swizzled rank-1 + bias
    float red[2][NE * NSV];      // swizzled k-split reduction
    float sin8[2][NE][8];
    float env[2][NE];
    float rl[2][NE][3];
    float ldet[2][32];
    float sgn[2][32];
};

union U64 { unsigned long long u; float2 f; };

__device__ __forceinline__ void ffma2(unsigned long long &d, unsigned long long a, unsigned long long b) {
    asm("fma.rn.f32x2 %0, %1, %2, %0;" : "+l"(d) : "l"(a), "l"(b));
}
__device__ __forceinline__ unsigned long long dup2(float x) {
    unsigned long long r;
    asm("mov.b64 %0, {%1, %1};" : "=l"(r) : "f"(x));
    return r;
}
__device__ __forceinline__ int swz(int c)  { return c ^ (c >> 5); }   // bijective on [0,256)
__device__ __forceinline__ int swzo(int o) { return o ^ (o >> 5); }   // bijective on [0,112)

__global__ void __launch_bounds__(512, 1)
ansatz_kernel(const float* __restrict__ r,
              const float* __restrict__ s_w0, const float* __restrict__ s_b0,
              const float* __restrict__ s_w,  const float* __restrict__ s_b,
              const float* __restrict__ p_w0, const float* __restrict__ p_b0,
              const float* __restrict__ p_w,  const float* __restrict__ p_b,
              const float* __restrict__ va_w, const float* __restrict__ va_b,
              const float* __restrict__ wu_w, const float* __restrict__ wu_b,
              const float* __restrict__ wd_w, const float* __restrict__ wd_b,
              const float* __restrict__ wf_w,
              float* __restrict__ out, int nb)
{
    extern __shared__ char smem_raw[];
    Smem& s = *reinterpret_cast<Smem*>(smem_raw);

    const int t    = threadIdx.x;
    const int lane = t & 31;
    const int wid  = t >> 5;
    const int b0   = blockIdx.x * 2;
    const float inv7 = 1.0f / 7.0f;

    // thread (el, c) view for 256-column phases
    const int tel = t >> 8;        // 0/1
    const int tc  = t & 255;

    // ---------------- Phase 0: geometry for both elements ----------------
    for (int q = t; q < 2 * NE * 3; q += 512) {
        int el = q / (NE * 3);
        int bel = b0 + el; if (bel >= nb) bel = nb - 1;
        ((float*)s.rl[el])[q - el * (NE * 3)] = r[bel * (NE * 3) + (q - el * (NE * 3))];
    }
    __syncthreads();

    if (t < 2 * NE) {
        int el = t / NE, e = t - el * NE;
        float x = s.rl[el][e][0], y = s.rl[el][e][1], z = s.rl[el][e][2];
        float ev = 0.f;
        #pragma unroll
        for (int a = 0; a < 2; ++a) {
            float dz = z - (a ? 1.4f : 0.0f);
            float len = sqrtf(x * x + y * y + dz * dz);
            s.sin8[el][e][a * 4 + 0] = x;
            s.sin8[el][e][a * 4 + 1] = y;
            s.sin8[el][e][a * 4 + 2] = dz;
            s.sin8[el][e][a * 4 + 3] = len;
            ev += expf(-len);
        }
        s.env[el][e] = ev;
    }
    if (t < 2 * NPAIR) {
        int el = t / NPAIR, pr = t - el * NPAIR;
        int i = pr / 14, j = pr - i * 14;
        float dx = s.rl[el][j][0] - s.rl[el][i][0];
        float dy = s.rl[el][j][1] - s.rl[el][i][1];
        float dz = s.rl[el][j][2] - s.rl[el][i][2];
        float ax = dx, ay = dy, az = dz;
        if (i == j) { ax += 1.f; ay += 1.f; az += 1.f; }
        float len = sqrtf(ax * ax + ay * ay + az * az);
        s.scr[el][pr * 4 + 0] = dx; s.scr[el][pr * 4 + 1] = dy;
        s.scr[el][pr * 4 + 2] = dz; s.scr[el][pr * 4 + 3] = len;
    }
    __syncthreads();

    // layer-0 means
    if (t < 32) {
        int el = t >> 4, q = t & 15;
        int k = q & 7, half = q >> 3;
        float su = 0.f;
        #pragma unroll
        for (int e = 0; e < 7; ++e) su += s.sin8[el][half * 7 + e][k];
        s.mumd[el][half * 8 + k] = su * inv7;
    }
    if (t >= 64 && t < 64 + 224) {
        int q2 = t - 64;
        int el = q2 / 112, q = q2 - el * 112;
        int dn = (q >= 56) ? 1 : 0;
        int qq = q - dn * 56;
        int e = qq >> 2, k = qq & 3;
        int i0 = dn ? 7 : 0;
        float su = 0.f;
        #pragma unroll
        for (int ii = 0; ii < 7; ++ii) su += s.scr[el][((i0 + ii) * 14 + e) * 4 + k];
        s.scr[el][784 + dn * 56 + e * 4 + k] = su * inv7;
    }
    __syncthreads();

    // ---------------- Layer 0 ----------------
    {
        float pnew[32];
        const bool prow = (t < 2 * NPAIR);
        int pel = 0, pr = 0;
        if (prow) {
            pel = t / NPAIR; pr = t - pel * NPAIR;
            const float* pin = s.scr[pel] + pr * 4;
            float r0 = pin[0], r1 = pin[1], r2 = pin[2], r3 = pin[3];
            #pragma unroll
            for (int c2 = 0; c2 < 32; ++c2) {
                float v = p_b0[c2]
                        + r0 * p_w0[0 * 32 + c2] + r1 * p_w0[1 * 32 + c2]
                        + r2 * p_w0[2 * 32 + c2] + r3 * p_w0[3 * 32 + c2];
                pnew[c2] = tanhf(v);
            }
        }
        // electron stream: (tel, tc)
        float cm0 = s_b0[tc];
        #pragma unroll
        for (int k = 0; k < 8; ++k)
            cm0 += s.mumd[tel][k] * s_w0[(8 + k) * 256 + tc] + s.mumd[tel][8 + k] * s_w0[(16 + k) * 256 + tc];
        float acc[NE];
        #pragma unroll
        for (int e = 0; e < NE; ++e) acc[e] = cm0;
        #pragma unroll
        for (int k = 0; k < 8; ++k) {
            float w = s_w0[k * 256 + tc];
            #pragma unroll
            for (int e = 0; e < NE; ++e) acc[e] += s.sin8[tel][e][k] * w;
        }
        const float* pu0 = s.scr[tel] + 784;
        const float* pd0 = s.scr[tel] + 840;
        #pragma unroll
        for (int k = 0; k < 4; ++k) {
            float wuv = s_w0[(24 + k) * 256 + tc];
            float wdv = s_w0[(28 + k) * 256 + tc];
            #pragma unroll
            for (int e = 0; e < NE; ++e)
                acc[e] += pu0[e * 4 + k] * wuv + pd0[e * 4 + k] * wdv;
        }
        if (prow) {
            #pragma unroll
            for (int c2 = 0; c2 < 32; ++c2) s.pv[pel][pr * NPVs + c2] = pnew[c2];
        }
        #pragma unroll
        for (int e = 0; e < NE; ++e) s.sv[tel][e][tc] = tanhf(acc[e]);
    }
    __syncthreads();

    // ---------------- FB layers + final va ----------------
    for (int il = 0; il <= NFB; ++il) {
        const bool last = (il == NFB);
        const float* WL = last ? va_w : (s_w + il * (832 * 256));
        const float* bL = last ? va_b : (s_b + il * 256);
        const float* PW = p_w + il * (32 * 32);
        const float* Pb = p_b + il * 32;

        // (a) means + cm init + zero red
        {
            float su = 0.f, sd = 0.f;
            #pragma unroll
            for (int e = 0; e < 7; ++e) { su += s.sv[tel][e][tc]; sd += s.sv[tel][7 + e][tc]; }
            s.mumd[tel][tc]       = su * inv7;
            s.mumd[tel][256 + tc] = sd * inv7;
            s.cm[tel][swz(tc)]    = bL[tc];
        }
        for (int idx = t; idx < 2 * 896; idx += 512) {
            int el = idx / 896, q2 = idx - el * 896;
            int dn = (q2 >= 448) ? 1 : 0;
            int q = q2 - dn * 448;
            int e = q >> 5, k = q & 31;
            int i0 = dn ? 7 : 0;
            float su = 0.f;
            #pragma unroll
            for (int ii = 0; ii < 7; ++ii) su += s.pv[el][((i0 + ii) * 14 + e) * NPVs + k];
            s.scr[el][q2] = su * inv7;
        }
        for (int q = t; q < 2 * NE * NSV; q += 512) ((float*)s.red)[q] = 0.f;
        __syncthreads();

        // (b) pair GEMM
        if (!last && t < 2 * NPAIR) {
            int el = t / NPAIR, pr = t - el * NPAIR;
            float row[32];
            #pragma unroll
            for (int k = 0; k < 32; ++k) row[k] = s.pv[el][pr * NPVs + k];
            unsigned long long o[16];
            const ulonglong2* pb2 = (const ulonglong2*)Pb;
            #pragma unroll
            for (int q = 0; q < 8; ++q) {
                ulonglong2 bv = pb2[q];
                o[2 * q] = bv.x; o[2 * q + 1] = bv.y;
            }
            #pragma unroll
            for (int k = 0; k < 32; ++k) {
                unsigned long long rk = dup2(row[k]);
                const ulonglong2* w2 = (const ulonglong2*)(PW + k * 32);
                #pragma unroll
                for (int q = 0; q < 8; ++q) {
                    ulonglong2 wv = w2[q];
                    ffma2(o[2 * q], rk, wv.x);
                    ffma2(o[2 * q + 1], rk, wv.y);
                }
            }
            #pragma unroll
            for (int q = 0; q < 16; ++q) {
                U64 u; u.u = o[q];
                s.pv[el][pr * NPVs + 2 * q]     = tanhf(u.f.x) + row[2 * q];
                s.pv[el][pr * NPVs + 2 * q + 1] = tanhf(u.f.y) + row[2 * q + 1];
            }
        }

        // (c) cm rank-1 GEMM: warp wid handles rows [wid*32, wid*32+32), both elems
        {
            const int kb2 = wid * 32;
            const int c0m = lane * 8;
            unsigned long long ca[2][4];
            #pragma unroll
            for (int el = 0; el < 2; ++el)
                #pragma unroll
                for (int p = 0; p < 4; ++p) ca[el][p] = 0ull;
            #pragma unroll 2
            for (int kk = 0; kk < 32; kk += 4) {
                const int k = kb2 + kk;
                const float* wp = WL + (256 + k) * 256 + c0m;
                ulonglong2 wA0 = *(const ulonglong2*)(wp);
                ulonglong2 wB0 = *(const ulonglong2*)(wp + 4);
                ulonglong2 wA1 = *(const ulonglong2*)(wp + 256);
                ulonglong2 wB1 = *(const ulonglong2*)(wp + 260);
                ulonglong2 wA2 = *(const ulonglong2*)(wp + 512);
                ulonglong2 wB2 = *(const ulonglong2*)(wp + 516);
                ulonglong2 wA3 = *(const ulonglong2*)(wp + 768);
                ulonglong2 wB3 = *(const ulonglong2*)(wp + 772);
                #pragma unroll
                for (int el = 0; el < 2; ++el) {
                    float4 m4 = *(const float4*)&s.mumd[el][k];
                    unsigned long long d;
                    d = dup2(m4.x); ffma2(ca[el][0], d, wA0.x); ffma2(ca[el][1], d, wA0.y);
                                    ffma2(ca[el][2], d, wB0.x); ffma2(ca[el][3], d, wB0.y);
                    d = dup2(m4.y); ffma2(ca[el][0], d, wA1.x); ffma2(ca[el][1], d, wA1.y);
                                    ffma2(ca[el][2], d, wB1.x); ffma2(ca[el][3], d, wB1.y);
                    d = dup2(m4.z); ffma2(ca[el][0], d, wA2.x); ffma2(ca[el][1], d, wA2.y);
                                    ffma2(ca[el][2], d, wB2.x); ffma2(ca[el][3], d, wB2.y);
                    d = dup2(m4.w); ffma2(ca[el][0], d, wA3.x); ffma2(ca[el][1], d, wA3.y);
                                    ffma2(ca[el][2], d, wB3.x); ffma2(ca[el][3], d, wB3.y);
                }
            }
            #pragma unroll
            for (int el = 0; el < 2; ++el)
                #pragma unroll
                for (int p = 0; p < 4; ++p) {
                    U64 u; u.u = ca[el][p];
                    atomicAdd(&s.cm[el][swz(c0m + 2 * p)],     u.f.x);
                    atomicAdd(&s.cm[el][swz(c0m + 2 * p + 1)], u.f.y);
                }
        }

        // (d) main electron GEMM: warp (eh, ch, kh), both elems, 4-k batched LDS
        {
            const int kh  = wid & 3;
            const int ch  = (wid >> 2) & 1;
            const int eh2 = wid >> 3;
            const int e0  = eh2 * 7;
            const int c0  = ch * 128 + lane * 4;
            unsigned long long acc[2][7][2];
            #pragma unroll
            for (int el = 0; el < 2; ++el)
                #pragma unroll
                for (int i = 0; i < 7; ++i) { acc[el][i][0] = 0ull; acc[el][i][1] = 0ull; }

            const int kb = kh * 64;
            #pragma unroll 2
            for (int kk = 0; kk < 64; kk += 4) {
                const int k = kb + kk;
                const float* wp = WL + k * 256 + c0;
                ulonglong2 w0 = *(const ulonglong2*)(wp);
                ulonglong2 w1 = *(const ulonglong2*)(wp + 256);
                ulonglong2 w2 = *(const ulonglong2*)(wp + 512);
                ulonglong2 w3 = *(const ulonglong2*)(wp + 768);
                #pragma unroll
                for (int i = 0; i < 7; ++i) {
                    float4 a0 = *(const float4*)&s.sv[0][e0 + i][k];
                    float4 a1 = *(const float4*)&s.sv[1][e0 + i][k];
                    unsigned long long d;
                    d = dup2(a0.x); ffma2(acc[0][i][0], d, w0.x); ffma2(acc[0][i][1], d, w0.y);
                    d = dup2(a0.y); ffma2(acc[0][i][0], d, w1.x); ffma2(acc[0][i][1], d, w1.y);
                    d = dup2(a0.z); ffma2(acc[0][i][0], d, w2.x); ffma2(acc[0][i][1], d, w2.y);
                    d = dup2(a0.w); ffma2(acc[0][i][0], d, w3.x); ffma2(acc[0][i][1], d, w3.y);
                    d = dup2(a1.x); ffma2(acc[1][i][0], d, w0.x); ffma2(acc[1][i][1], d, w0.y);
                    d = dup2(a1.y); ffma2(acc[1][i][0], d, w1.x); ffma2(acc[1][i][1], d, w1.y);
                    d = dup2(a1.z); ffma2(acc[1][i][0], d, w2.x); ffma2(acc[1][i][1], d, w2.y);
                    d = dup2(a1.w); ffma2(acc[1][i][0], d, w3.x); ffma2(acc[1][i][1], d, w3.y);
                }
            }
            // pu/pd extension rows: kh handles k in [kh*8, kh*8+8)  (32 rows / 4 kh groups)
            #pragma unroll
            for (int blk = 0; blk < 2; ++blk) {   // 0 -> pu (rows 768..799), 1 -> pd (rows 800..831)
                const int rowb = 768 + blk * 32;
                const int scrb = blk * 448;
                #pragma unroll
                for (int kk = 0; kk < 8; kk += 4) {
                    const int k = kh * 8 + kk;
                    const float* wp = WL + (rowb + k) * 256 + c0;
                    ulonglong2 w0 = *(const ulonglong2*)(wp);
                    ulonglong2 w1 = *(const ulonglong2*)(wp + 256);
                    ulonglong2 w2 = *(const ulonglong2*)(wp + 512);
                    ulonglong2 w3 = *(const ulonglong2*)(wp + 768);
                    #pragma unroll
                    for (int i = 0; i < 7; ++i) {
                        float4 a0 = *(const float4*)&s.scr[0][scrb + (e0 + i) * 32 + k];
                        float4 a1 = *(const float4*)&s.scr[1][scrb + (e0 + i) * 32 + k];
                        unsigned long long d;
                        d = dup2(a0.x); ffma2(acc[0][i][0], d, w0.x); ffma2(acc[0][i][1], d, w0.y);
                        d = dup2(a0.y); ffma2(acc[0][i][0], d, w1.x); ffma2(acc[0][i][1], d, w1.y);
                        d = dup2(a0.z); ffma2(acc[0][i][0], d, w2.x); ffma2(acc[0][i][1], d, w2.y);
                        d = dup2(a0.w); ffma2(acc[0][i][0], d, w3.x); ffma2(acc[0][i][1], d, w3.y);
                        d = dup2(a1.x); ffma2(acc[1][i][0], d, w0.x); ffma2(acc[1][i][1], d, w0.y);
                        d = dup2(a1.y); ffma2(acc[1][i][0], d, w1.x); ffma2(acc[1][i][1], d, w1.y);
                        d = dup2(a1.z); ffma2(acc[1][i][0], d, w2.x); ffma2(acc[1][i][1], d, w2.y);
                        d = dup2(a1.w); ffma2(acc[1][i][0], d, w3.x); ffma2(acc[1][i][1], d, w3.y);
                    }
                }
            }
            // k-split reduction via swizzled shared atomics
            #pragma unroll
            for (int el = 0; el < 2; ++el)
                #pragma unroll
                for (int i = 0; i < 7; ++i)
                    #pragma unroll
                    for (int p = 0; p < 2; ++p) {
                        U64 u; u.u = acc[el][i][p];
                        atomicAdd(&s.red[el][(e0 + i) * NSV + swz(c0 + 2 * p)],     u.f.x);
                        atomicAdd(&s.red[el][(e0 + i) * NSV + swz(c0 + 2 * p + 1)], u.f.y);
                    }
        }
        __syncthreads();

        // (e) epilogue
        {
            const int cs = swz(tc);
            const float cmv = s.cm[tel][cs];
            #pragma unroll
            for (int e = 0; e < NE; ++e) {
                float v = tanhf(s.red[tel][e * NSV + cs] + cmv);
                s.sv[tel][e][tc] = last ? v : (v + s.sv[tel][e][tc]);
            }
        }
        __syncthreads();
    }

    // ---------------- Orbitals ----------------
    for (int idx = t; idx < 2 * NE * NORB; idx += 512) {
        int el = idx / (NE * NORB), q = idx - el * (NE * NORB);
        int e = q / NORB, o = q - e * NORB;
        s.pv[el][e * NORB + swzo(o)] = (e < 7) ? wu_b[o] : wd_b[o];
    }
    __syncthreads();
    {
        const int kh  = wid & 3;
        const int eh2 = (wid >> 2) & 1;
        const int oel = wid >> 3;
        const int e0  = eh2 * 7;
        const int oc0 = lane * 4;
        if (oc0 < NORB) {
            const float* W = eh2 ? wd_w : wu_w;
            unsigned long long oa[7][2];
            #pragma unroll
            for (int i = 0; i < 7; ++i) { oa[i][0] = 0ull; oa[i][1] = 0ull; }
            const int kb = kh * 64;
            #pragma unroll 2
            for (int kk = 0; kk < 64; kk += 4) {
                const int k = kb + kk;
                ulonglong2 w0 = *(const ulonglong2*)(W + (k + 0) * NORB + oc0);
                ulonglong2 w1 = *(const ulonglong2*)(W + (k + 1) * NORB + oc0);
                ulonglong2 w2 = *(const ulonglong2*)(W + (k + 2) * NORB + oc0);
                ulonglong2 w3 = *(const ulonglong2*)(W + (k + 3) * NORB + oc0);
                #pragma unroll
                for (int i = 0; i < 7; ++i) {
                    float4 a = *(const float4*)&s.sv[oel][e0 + i][k];
                    unsigned long long d;
                    d = dup2(a.x); ffma2(oa[i][0], d, w0.x); ffma2(oa[i][1], d, w0.y);
                    d = dup2(a.y); ffma2(oa[i][0], d, w1.x); ffma2(oa[i][1], d, w1.y);
                    d = dup2(a.z); ffma2(oa[i][0], d, w2.x); ffma2(oa[i][1], d, w2.y);
                    d = dup2(a.w); ffma2(oa[i][0], d, w3.x); ffma2(oa[i][1], d, w3.y);
                }
            }
            #pragma unroll
            for (int i = 0; i < 7; ++i)
                #pragma unroll
                for (int p = 0; p < 2; ++p) {
                    U64 u; u.u = oa[i][p];
                    int o0 = oc0 + 2 * p;
                    atomicAdd(&s.pv[oel][(e0 + i) * NORB + swzo(o0)],     u.f.x);
                    atomicAdd(&s.pv[oel][(e0 + i) * NORB + swzo(o0 + 1)], u.f.y);
                }
        }
    }
    __syncthreads();
    for (int idx = t; idx < 2 * NE * NORB; idx += 512) {
        int el = idx / (NE * NORB), q = idx - el * (NE * NORB);
        int e = q / NORB;
        s.pv[el][q] *= s.env[el][e];
    }
    __syncthreads();

    // ---------------- 2 x 32 slogdets of 7x7 ----------------
    if (t < 64) {
        const int el = t >> 5, tt = t & 31;
        const int sp = tt >> 4, d = tt & 15;
        float m[7][7];
        #pragma unroll
        for (int j = 0; j < 7; ++j) {
            int og = swzo(j * 16 + d);
            #pragma unroll
            for (int i = 0; i < 7; ++i)
                m[j][i] = s.pv[el][(sp * 7 + i) * NORB + og];
        }
        float ld = 0.f, sg = 1.f;
        #pragma unroll
        for (int col = 0; col < 7; ++col) {
            #pragma unroll
            for (int rr = col + 1; rr < 7; ++rr) {
                if (fabsf(m[rr][col]) > fabsf(m[col][col])) {
                    sg = -sg;
                    #pragma unroll
                    for (int cc = 0; cc < 7; ++cc) {
                        float tmp = m[col][cc]; m[col][cc] = m[rr][cc]; m[rr][cc] = tmp;
                    }
                }
            }
            float piv = m[col][col];
            sg = (piv < 0.f) ? -sg : sg;
            ld += logf(fabsf(piv));
            float inv = 1.f / piv;
            #pragma unroll
            for (int rr = col + 1; rr < 7; ++rr) {
                float f = m[rr][col] * inv;
                #pragma unroll
                for (int cc = col + 1; cc < 7; ++cc)
                    m[rr][cc] -= f * m[col][cc];
            }
        }
        s.ldet[el][tt] = ld;
        s.sgn[el][tt] = sg;
    }
    __syncthreads();

    if (t < 2 && (b0 + t) < nb) {
        const int el = t;
        float l[16], mx = -3.4e38f;
        #pragma unroll
        for (int d = 0; d < 16; ++d) {
            l[d] = s.ldet[el][d] + s.ldet[el][16 + d];
            mx = fmaxf(mx, l[d]);
        }
        float psi = 0.f;
        #pragma unroll
        for (int d = 0; d < 16; ++d)
            psi += s.sgn[el][d] * s.sgn[el][16 + d] * expf(l[d] - mx) * wf_w[d];
        out[b0 + el] = logf(fabsf(psi)) + mx;
    }
}

extern "C" void kernel_launch(void* const* d_in, const int* in_sizes, int n_in,
                              void* d_out, int out_size)
{
    const float* r    = (const float*)d_in[0];
    const float* s_w0 = (const float*)d_in[1];
    const float* s_b0 = (const float*)d_in[2];
    const float* s_w  = (const float*)d_in[3];
    const float* s_b  = (const float*)d_in[4];
    const float* p_w0 = (const float*)d_in[5];
    const float* p_b0 = (const float*)d_in[6];
    const float* p_w  = (const float*)d_in[7];
    const float* p_b  = (const float*)d_in[8];
    const float* va_w = (const float*)d_in[9];
    const float* va_b = (const float*)d_in[10];
    const float* wu_w = (const float*)d_in[11];
    const float* wu_b = (const float*)d_in[12];
    const float* wd_w = (const float*)d_in[13];
    const float* wd_b = (const float*)d_in[14];
    const float* wf_w = (const float*)d_in[15];

    const int nb  = in_sizes[0] / (14 * 3);
    const int nb2 = (nb + 1) / 2;
    const int smem = (int)sizeof(Smem);
    cudaFuncSetAttribute(ansatz_kernel, cudaFuncAttributeMaxDynamicSharedMemorySize, smem);
    ansatz_kernel<<<nb2, 512, smem>>>(r, s_w0, s_b0, s_w, s_b, p_w0, p_b0, p_w, p_b,
                                      va_w, va_b, wu_w, wu_b, wd_w, wd_b, wf_w,
                                      (float*)d_out, nb);
}

// round 5
// speedup vs baseline: 1.4416x; 1.0477x over previous
#include <cuda_runtime.h>
#include <math.h>

#define NE    14
#define NSV   256
#define NPVs  33
#define NPAIR 196
#define NORB  112
#define NFB   3

struct __align__(16) Smem {
    float sv[2][NE][NSV];        // 28672 B
    float pv[2][NPAIR * NPVs];   // 51744 B (reused as orbm[14][112] swizzled)
    float red[4][2][NE][NSV];    // 114688 B: k-split partials (plain stores, no atomics)
    float scr[2][896];           // pu/pd means; layer0: pin + pu0/pd0
    float mumd[2][512];          // mu | md
    float cm[2][NSV];            // swizzled rank-1 + bias (small atomic set)
    float sin8[2][NE][8];
    float env[2][NE];
    float rl[2][NE][3];
    float ldet[2][32];
    float sgn[2][32];
};

union U64 { unsigned long long u; float2 f; };

__device__ __forceinline__ void ffma2(unsigned long long &d, unsigned long long a, unsigned long long b) {
    asm("fma.rn.f32x2 %0, %1, %2, %0;" : "+l"(d) : "l"(a), "l"(b));
}
__device__ __forceinline__ unsigned long long dup2(float x) {
    unsigned long long r;
    asm("mov.b64 %0, {%1, %1};" : "=l"(r) : "f"(x));
    return r;
}
__device__ __forceinline__ int swz(int c)  { return c ^ (c >> 5); }   // bijective on [0,256)
__device__ __forceinline__ int swzo(int o) { return o ^ (o >> 5); }   // bijective on [0,112)

// exact identity (e^{2x}-1)/(e^{2x}+1); error ~1e-7 abs from __expf/__fdividef
__device__ __forceinline__ float fast_tanh(float x) {
    float e = __expf(2.0f * x);
    return 1.0f - __fdividef(2.0f, e + 1.0f);
}

__global__ void __launch_bounds__(512, 1)
ansatz_kernel(const float* __restrict__ r,
              const float* __restrict__ s_w0, const float* __restrict__ s_b0,
              const float* __restrict__ s_w,  const float* __restrict__ s_b,
              const float* __restrict__ p_w0, const float* __restrict__ p_b0,
              const float* __restrict__ p_w,  const float* __restrict__ p_b,
              const float* __restrict__ va_w, const float* __restrict__ va_b,
              const float* __restrict__ wu_w, const float* __restrict__ wu_b,
              const float* __restrict__ wd_w, const float* __restrict__ wd_b,
              const float* __restrict__ wf_w,
              float* __restrict__ out, int nb)
{
    extern __shared__ char smem_raw[];
    Smem& s = *reinterpret_cast<Smem*>(smem_raw);

    const int t    = threadIdx.x;
    const int lane = t & 31;
    const int wid  = t >> 5;
    const int b0   = blockIdx.x * 2;
    const float inv7 = 1.0f / 7.0f;

    const int tel = t >> 8;        // 0/1
    const int tc  = t & 255;

    // ---------------- Phase 0: geometry ----------------
    for (int q = t; q < 2 * NE * 3; q += 512) {
        int el = q / (NE * 3);
        int bel = b0 + el; if (bel >= nb) bel = nb - 1;
        ((float*)s.rl[el])[q - el * (NE * 3)] = r[bel * (NE * 3) + (q - el * (NE * 3))];
    }
    __syncthreads();

    if (t < 2 * NE) {
        int el = t / NE, e = t - el * NE;
        float x = s.rl[el][e][0], y = s.rl[el][e][1], z = s.rl[el][e][2];
        float ev = 0.f;
        #pragma unroll
        for (int a = 0; a < 2; ++a) {
            float dz = z - (a ? 1.4f : 0.0f);
            float len = sqrtf(x * x + y * y + dz * dz);
            s.sin8[el][e][a * 4 + 0] = x;
            s.sin8[el][e][a * 4 + 1] = y;
            s.sin8[el][e][a * 4 + 2] = dz;
            s.sin8[el][e][a * 4 + 3] = len;
            ev += __expf(-len);
        }
        s.env[el][e] = ev;
    }
    if (t < 2 * NPAIR) {
        int el = t / NPAIR, pr = t - el * NPAIR;
        int i = pr / 14, j = pr - i * 14;
        float dx = s.rl[el][j][0] - s.rl[el][i][0];
        float dy = s.rl[el][j][1] - s.rl[el][i][1];
        float dz = s.rl[el][j][2] - s.rl[el][i][2];
        float ax = dx, ay = dy, az = dz;
        if (i == j) { ax += 1.f; ay += 1.f; az += 1.f; }
        float len = sqrtf(ax * ax + ay * ay + az * az);
        s.scr[el][pr * 4 + 0] = dx; s.scr[el][pr * 4 + 1] = dy;
        s.scr[el][pr * 4 + 2] = dz; s.scr[el][pr * 4 + 3] = len;
    }
    __syncthreads();

    // layer-0 means
    if (t < 32) {
        int el = t >> 4, q = t & 15;
        int k = q & 7, half = q >> 3;
        float su = 0.f;
        #pragma unroll
        for (int e = 0; e < 7; ++e) su += s.sin8[el][half * 7 + e][k];
        s.mumd[el][half * 8 + k] = su * inv7;
    }
    if (t >= 64 && t < 64 + 224) {
        int q2 = t - 64;
        int el = q2 / 112, q = q2 - el * 112;
        int dn = (q >= 56) ? 1 : 0;
        int qq = q - dn * 56;
        int e = qq >> 2, k = qq & 3;
        int i0 = dn ? 7 : 0;
        float su = 0.f;
        #pragma unroll
        for (int ii = 0; ii < 7; ++ii) su += s.scr[el][((i0 + ii) * 14 + e) * 4 + k];
        s.scr[el][784 + dn * 56 + e * 4 + k] = su * inv7;
    }
    __syncthreads();

    // ---------------- Layer 0 ----------------
    {
        float pnew[32];
        const bool prow = (t < 2 * NPAIR);
        int pel = 0, pr = 0;
        if (prow) {
            pel = t / NPAIR; pr = t - pel * NPAIR;
            const float* pin = s.scr[pel] + pr * 4;
            float r0 = pin[0], r1 = pin[1], r2 = pin[2], r3 = pin[3];
            #pragma unroll
            for (int c2 = 0; c2 < 32; ++c2) {
                float v = p_b0[c2]
                        + r0 * p_w0[0 * 32 + c2] + r1 * p_w0[1 * 32 + c2]
                        + r2 * p_w0[2 * 32 + c2] + r3 * p_w0[3 * 32 + c2];
                pnew[c2] = fast_tanh(v);
            }
        }
        float cm0 = s_b0[tc];
        #pragma unroll
        for (int k = 0; k < 8; ++k)
            cm0 += s.mumd[tel][k] * s_w0[(8 + k) * 256 + tc] + s.mumd[tel][8 + k] * s_w0[(16 + k) * 256 + tc];
        float acc[NE];
        #pragma unroll
        for (int e = 0; e < NE; ++e) acc[e] = cm0;
        #pragma unroll
        for (int k = 0; k < 8; ++k) {
            float w = s_w0[k * 256 + tc];
            #pragma unroll
            for (int e = 0; e < NE; ++e) acc[e] += s.sin8[tel][e][k] * w;
        }
        const float* pu0 = s.scr[tel] + 784;
        const float* pd0 = s.scr[tel] + 840;
        #pragma unroll
        for (int k = 0; k < 4; ++k) {
            float wuv = s_w0[(24 + k) * 256 + tc];
            float wdv = s_w0[(28 + k) * 256 + tc];
            #pragma unroll
            for (int e = 0; e < NE; ++e)
                acc[e] += pu0[e * 4 + k] * wuv + pd0[e * 4 + k] * wdv;
        }
        if (prow) {
            #pragma unroll
            for (int c2 = 0; c2 < 32; ++c2) s.pv[pel][pr * NPVs + c2] = pnew[c2];
        }
        #pragma unroll
        for (int e = 0; e < NE; ++e) s.sv[tel][e][tc] = fast_tanh(acc[e]);
    }
    __syncthreads();

    // ---------------- FB layers + final va ----------------
    for (int il = 0; il <= NFB; ++il) {
        const bool last = (il == NFB);
        const float* WL = last ? va_w : (s_w + il * (832 * 256));
        const float* bL = last ? va_b : (s_b + il * 256);
        const float* PW = p_w + il * (32 * 32);
        const float* Pb = p_b + il * 32;

        // (a) means + cm init
        {
            float su = 0.f, sd = 0.f;
            #pragma unroll
            for (int e = 0; e < 7; ++e) { su += s.sv[tel][e][tc]; sd += s.sv[tel][7 + e][tc]; }
            s.mumd[tel][tc]       = su * inv7;
            s.mumd[tel][256 + tc] = sd * inv7;
            s.cm[tel][swz(tc)]    = bL[tc];
        }
        for (int idx = t; idx < 2 * 896; idx += 512) {
            int el = idx / 896, q2 = idx - el * 896;
            int dn = (q2 >= 448) ? 1 : 0;
            int q = q2 - dn * 448;
            int e = q >> 5, k = q & 31;
            int i0 = dn ? 7 : 0;
            float su = 0.f;
            #pragma unroll
            for (int ii = 0; ii < 7; ++ii) su += s.pv[el][((i0 + ii) * 14 + e) * NPVs + k];
            s.scr[el][q2] = su * inv7;
        }
        __syncthreads();

        // (b) pair GEMM
        if (!last && t < 2 * NPAIR) {
            int el = t / NPAIR, pr = t - el * NPAIR;
            float row[32];
            #pragma unroll
            for (int k = 0; k < 32; ++k) row[k] = s.pv[el][pr * NPVs + k];
            unsigned long long o[16];
            const ulonglong2* pb2 = (const ulonglong2*)Pb;
            #pragma unroll
            for (int q = 0; q < 8; ++q) {
                ulonglong2 bv = pb2[q];
                o[2 * q] = bv.x; o[2 * q + 1] = bv.y;
            }
            #pragma unroll
            for (int k = 0; k < 32; ++k) {
                unsigned long long rk = dup2(row[k]);
                const ulonglong2* w2 = (const ulonglong2*)(PW + k * 32);
                #pragma unroll
                for (int q = 0; q < 8; ++q) {
                    ulonglong2 wv = w2[q];
                    ffma2(o[2 * q], rk, wv.x);
                    ffma2(o[2 * q + 1], rk, wv.y);
                }
            }
            #pragma unroll
            for (int q = 0; q < 16; ++q) {
                U64 u; u.u = o[q];
                s.pv[el][pr * NPVs + 2 * q]     = fast_tanh(u.f.x) + row[2 * q];
                s.pv[el][pr * NPVs + 2 * q + 1] = fast_tanh(u.f.y) + row[2 * q + 1];
            }
        }

        // (c) cm rank-1 GEMM (small atomic set)
        {
            const int kb2 = wid * 32;
            const int c0m = lane * 8;
            unsigned long long ca[2][4];
            #pragma unroll
            for (int el = 0; el < 2; ++el)
                #pragma unroll
                for (int p = 0; p < 4; ++p) ca[el][p] = 0ull;
            #pragma unroll 2
            for (int kk = 0; kk < 32; kk += 4) {
                const int k = kb2 + kk;
                const float* wp = WL + (256 + k) * 256 + c0m;
                ulonglong2 wA0 = *(const ulonglong2*)(wp);
                ulonglong2 wB0 = *(const ulonglong2*)(wp + 4);
                ulonglong2 wA1 = *(const ulonglong2*)(wp + 256);
                ulonglong2 wB1 = *(const ulonglong2*)(wp + 260);
                ulonglong2 wA2 = *(const ulonglong2*)(wp + 512);
                ulonglong2 wB2 = *(const ulonglong2*)(wp + 516);
                ulonglong2 wA3 = *(const ulonglong2*)(wp + 768);
                ulonglong2 wB3 = *(const ulonglong2*)(wp + 772);
                #pragma unroll
                for (int el = 0; el < 2; ++el) {
                    float4 m4 = *(const float4*)&s.mumd[el][k];
                    unsigned long long d;
                    d = dup2(m4.x); ffma2(ca[el][0], d, wA0.x); ffma2(ca[el][1], d, wA0.y);
                                    ffma2(ca[el][2], d, wB0.x); ffma2(ca[el][3], d, wB0.y);
                    d = dup2(m4.y); ffma2(ca[el][0], d, wA1.x); ffma2(ca[el][1], d, wA1.y);
                                    ffma2(ca[el][2], d, wB1.x); ffma2(ca[el][3], d, wB1.y);
                    d = dup2(m4.z); ffma2(ca[el][0], d, wA2.x); ffma2(ca[el][1], d, wA2.y);
                                    ffma2(ca[el][2], d, wB2.x); ffma2(ca[el][3], d, wB2.y);
                    d = dup2(m4.w); ffma2(ca[el][0], d, wA3.x); ffma2(ca[el][1], d, wA3.y);
                                    ffma2(ca[el][2], d, wB3.x); ffma2(ca[el][3], d, wB3.y);
                }
            }
            #pragma unroll
            for (int el = 0; el < 2; ++el)
                #pragma unroll
                for (int p = 0; p < 4; ++p) {
                    U64 u; u.u = ca[el][p];
                    atomicAdd(&s.cm[el][swz(c0m + 2 * p)],     u.f.x);
                    atomicAdd(&s.cm[el][swz(c0m + 2 * p + 1)], u.f.y);
                }
        }

        // (d) main electron GEMM: warp (eh, ch, kh), both elems, plain STS.128 partials
        {
            const int kh  = wid & 3;
            const int ch  = (wid >> 2) & 1;
            const int eh2 = wid >> 3;
            const int e0  = eh2 * 7;
            const int c0  = ch * 128 + lane * 4;
            unsigned long long acc[2][7][2];
            #pragma unroll
            for (int el = 0; el < 2; ++el)
                #pragma unroll
                for (int i = 0; i < 7; ++i) { acc[el][i][0] = 0ull; acc[el][i][1] = 0ull; }

            const int kb = kh * 64;
            #pragma unroll 2
            for (int kk = 0; kk < 64; kk += 4) {
                const int k = kb + kk;
                const float* wp = WL + k * 256 + c0;
                ulonglong2 w0 = *(const ulonglong2*)(wp);
                ulonglong2 w1 = *(const ulonglong2*)(wp + 256);
                ulonglong2 w2 = *(const ulonglong2*)(wp + 512);
                ulonglong2 w3 = *(const ulonglong2*)(wp + 768);
                #pragma unroll
                for (int i = 0; i < 7; ++i) {
                    float4 a0 = *(const float4*)&s.sv[0][e0 + i][k];
                    float4 a1 = *(const float4*)&s.sv[1][e0 + i][k];
                    unsigned long long d;
                    d = dup2(a0.x); ffma2(acc[0][i][0], d, w0.x); ffma2(acc[0][i][1], d, w0.y);
                    d = dup2(a0.y); ffma2(acc[0][i][0], d, w1.x); ffma2(acc[0][i][1], d, w1.y);
                    d = dup2(a0.z); ffma2(acc[0][i][0], d, w2.x); ffma2(acc[0][i][1], d, w2.y);
                    d = dup2(a0.w); ffma2(acc[0][i][0], d, w3.x); ffma2(acc[0][i][1], d, w3.y);
                    d = dup2(a1.x); ffma2(acc[1][i][0], d, w0.x); ffma2(acc[1][i][1], d, w0.y);
                    d = dup2(a1.y); ffma2(acc[1][i][0], d, w1.x); ffma2(acc[1][i][1], d, w1.y);
                    d = dup2(a1.z); ffma2(acc[1][i][0], d, w2.x); ffma2(acc[1][i][1], d, w2.y);
                    d = dup2(a1.w); ffma2(acc[1][i][0], d, w3.x); ffma2(acc[1][i][1], d, w3.y);
                }
            }
            // pu/pd extension rows: kh handles k in [kh*8, kh*8+8)
            #pragma unroll
            for (int blk = 0; blk < 2; ++blk) {
                const int rowb = 768 + blk * 32;
                const int scrb = blk * 448;
                #pragma unroll
                for (int kk = 0; kk < 8; kk += 4) {
                    const int k = kh * 8 + kk;
                    const float* wp = WL + (rowb + k) * 256 + c0;
                    ulonglong2 w0 = *(const ulonglong2*)(wp);
                    ulonglong2 w1 = *(const ulonglong2*)(wp + 256);
                    ulonglong2 w2 = *(const ulonglong2*)(wp + 512);
                    ulonglong2 w3 = *(const ulonglong2*)(wp + 768);
                    #pragma unroll
                    for (int i = 0; i < 7; ++i) {
                        float4 a0 = *(const float4*)&s.scr[0][scrb + (e0 + i) * 32 + k];
                        float4 a1 = *(const float4*)&s.scr[1][scrb + (e0 + i) * 32 + k];
                        unsigned long long d;
                        d = dup2(a0.x); ffma2(acc[0][i][0], d, w0.x); ffma2(acc[0][i][1], d, w0.y);
                        d = dup2(a0.y); ffma2(acc[0][i][0], d, w1.x); ffma2(acc[0][i][1], d, w1.y);
                        d = dup2(a0.z); ffma2(acc[0][i][0], d, w2.x); ffma2(acc[0][i][1], d, w2.y);
                        d = dup2(a0.w); ffma2(acc[0][i][0], d, w3.x); ffma2(acc[0][i][1], d, w3.y);
                        d = dup2(a1.x); ffma2(acc[1][i][0], d, w0.x); ffma2(acc[1][i][1], d, w0.y);
                        d = dup2(a1.y); ffma2(acc[1][i][0], d, w1.x); ffma2(acc[1][i][1], d, w1.y);
                        d = dup2(a1.z); ffma2(acc[1][i][0], d, w2.x); ffma2(acc[1][i][1], d, w2.y);
                        d = dup2(a1.w); ffma2(acc[1][i][0], d, w3.x); ffma2(acc[1][i][1], d, w3.y);
                    }
                }
            }
            // plain conflict-free STS.128 of partials (each warp owns its (kh,el,e,c) tile)
            #pragma unroll
            for (int el = 0; el < 2; ++el)
                #pragma unroll
                for (int i = 0; i < 7; ++i) {
                    U64 u0; u0.u = acc[el][i][0];
                    U64 u1; u1.u = acc[el][i][1];
                    float4 v4 = make_float4(u0.f.x, u0.f.y, u1.f.x, u1.f.y);
                    *reinterpret_cast<float4*>(&s.red[kh][el][e0 + i][c0]) = v4;
                }
        }
        __syncthreads();

        // (e) epilogue: sum 4 k-slots + cm, tanh + residual
        {
            const float cmv = s.cm[tel][swz(tc)];
            #pragma unroll
            for (int e = 0; e < NE; ++e) {
                float v = cmv + s.red[0][tel][e][tc] + s.red[1][tel][e][tc]
                              + s.red[2][tel][e][tc] + s.red[3][tel][e][tc];
                v = fast_tanh(v);
                s.sv[tel][e][tc] = last ? v : (v + s.sv[tel][e][tc]);
            }
        }
        __syncthreads();
    }

    // ---------------- Orbitals ----------------
    for (int idx = t; idx < 2 * NE * NORB; idx += 512) {
        int el = idx / (NE * NORB), q = idx - el * (NE * NORB);
        int e = q / NORB, o = q - e * NORB;
        s.pv[el][e * NORB + swzo(o)] = (e < 7) ? wu_b[o] : wd_b[o];
    }
    __syncthreads();
    {
        const int kh  = wid & 3;
        const int eh2 = (wid >> 2) & 1;
        const int oel = wid >> 3;
        const int e0  = eh2 * 7;
        const int oc0 = lane * 4;
        if (oc0 < NORB) {
            const float* W = eh2 ? wd_w : wu_w;
            unsigned long long oa[7][2];
            #pragma unroll
            for (int i = 0; i < 7; ++i) { oa[i][0] = 0ull; oa[i][1] = 0ull; }
            const int kb = kh * 64;
            #pragma unroll 2
            for (int kk = 0; kk < 64; kk += 4) {
                const int k = kb + kk;
                ulonglong2 w0 = *(const ulonglong2*)(W + (k + 0) * NORB + oc0);
                ulonglong2 w1 = *(const ulonglong2*)(W + (k + 1) * NORB + oc0);
                ulonglong2 w2 = *(const ulonglong2*)(W + (k + 2) * NORB + oc0);
                ulonglong2 w3 = *(const ulonglong2*)(W + (k + 3) * NORB + oc0);
                #pragma unroll
                for (int i = 0; i < 7; ++i) {
                    float4 a = *(const float4*)&s.sv[oel][e0 + i][k];
                    unsigned long long d;
                    d = dup2(a.x); ffma2(oa[i][0], d, w0.x); ffma2(oa[i][1], d, w0.y);
                    d = dup2(a.y); ffma2(oa[i][0], d, w1.x); ffma2(oa[i][1], d, w1.y);
                    d = dup2(a.z); ffma2(oa[i][0], d, w2.x); ffma2(oa[i][1], d, w2.y);
                    d = dup2(a.w); ffma2(oa[i][0], d, w3.x); ffma2(oa[i][1], d, w3.y);
                }
            }
            #pragma unroll
            for (int i = 0; i < 7; ++i)
                #pragma unroll
                for (int p = 0; p < 2; ++p) {
                    U64 u; u.u = oa[i][p];
                    int o0 = oc0 + 2 * p;
                    atomicAdd(&s.pv[oel][(e0 + i) * NORB + swzo(o0)],     u.f.x);
                    atomicAdd(&s.pv[oel][(e0 + i) * NORB + swzo(o0 + 1)], u.f.y);
                }
        }
    }
    __syncthreads();
    for (int idx = t; idx < 2 * NE * NORB; idx += 512) {
        int el = idx / (NE * NORB), q = idx - el * (NE * NORB);
        int e = q / NORB;
        s.pv[el][q] *= s.env[el][e];
    }
    __syncthreads();

    // ---------------- 2 x 32 slogdets of 7x7 ----------------
    if (t < 64) {
        const int el = t >> 5, tt = t & 31;
        const int sp = tt >> 4, d = tt & 15;
        float m[7][7];
        #pragma unroll
        for (int j = 0; j < 7; ++j) {
            int og = swzo(j * 16 + d);
            #pragma unroll
            for (int i = 0; i < 7; ++i)
                m[j][i] = s.pv[el][(sp * 7 + i) * NORB + og];
        }
        float ld = 0.f, sg = 1.f;
        #pragma unroll
        for (int col = 0; col < 7; ++col) {
            #pragma unroll
            for (int rr = col + 1; rr < 7; ++rr) {
                if (fabsf(m[rr][col]) > fabsf(m[col][col])) {
                    sg = -sg;
                    #pragma unroll
                    for (int cc = 0; cc < 7; ++cc) {
                        float tmp = m[col][cc]; m[col][cc] = m[rr][cc]; m[rr][cc] = tmp;
                    }
                }
            }
            float piv = m[col][col];
            sg = (piv < 0.f) ? -sg : sg;
            ld += __logf(fabsf(piv));
            float inv = 1.f / piv;
            #pragma unroll
            for (int rr = col + 1; rr < 7; ++rr) {
                float f = m[rr][col] * inv;
                #pragma unroll
                for (int cc = col + 1; cc < 7; ++cc)
                    m[rr][cc] -= f * m[col][cc];
            }
        }
        s.ldet[el][tt] = ld;
        s.sgn[el][tt] = sg;
    }
    __syncthreads();

    if (t < 2 && (b0 + t) < nb) {
        const int el = t;
        float l[16], mx = -3.4e38f;
        #pragma unroll
        for (int d = 0; d < 16; ++d) {
            l[d] = s.ldet[el][d] + s.ldet[el][16 + d];
            mx = fmaxf(mx, l[d]);
        }
        float psi = 0.f;
        #pragma unroll
        for (int d = 0; d < 16; ++d)
            psi += s.sgn[el][d] * s.sgn[el][16 + d] * __expf(l[d] - mx) * wf_w[d];
        out[b0 + el] = __logf(fabsf(psi)) + mx;
    }
}

extern "C" void kernel_launch(void* const* d_in, const int* in_sizes, int n_in,
                              void* d_out, int out_size)
{
    const float* r    = (const float*)d_in[0];
    const float* s_w0 = (const float*)d_in[1];
    const float* s_b0 = (const float*)d_in[2];
    const float* s_w  = (const float*)d_in[3];
    const float* s_b  = (const float*)d_in[4];
    const float* p_w0 = (const float*)d_in[5];
    const float* p_b0 = (const float*)d_in[6];
    const float* p_w  = (const float*)d_in[7];
    const float* p_b  = (const float*)d_in[8];
    const float* va_w = (const float*)d_in[9];
    const float* va_b = (const float*)d_in[10];
    const float* wu_w = (const float*)d_in[11];
    const float* wu_b = (const float*)d_in[12];
    const float* wd_w = (const float*)d_in[13];
    const float* wd_b = (const float*)d_in[14];
    const float* wf_w = (const float*)d_in[15];

    const int nb  = in_sizes[0] / (14 * 3);
    const int nb2 = (nb + 1) / 2;
    const int smem = (int)sizeof(Smem);
    cudaFuncSetAttribute(ansatz_kernel, cudaFuncAttributeMaxDynamicSharedMemorySize, smem);
    ansatz_kernel<<<nb2, 512, smem>>>(r, s_w0, s_b0, s_w, s_b, p_w0, p_b0, p_w, p_b,
                                      va_w, va_b, wu_w, wu_b, wd_w, wd_b, wf_w,
                                      (float*)d_out, nb);
}